// round 3
// baseline (speedup 1.0000x reference)
#include <cuda_runtime.h>
#include <cuda_bf16.h>
#include <cstdint>
#include <cstdio>

// Problem constants
#define BB 4
#define SS 2048
#define DD 1024
#define HH 16
#define DK 64
#define D3 3072
#define MM (BB*SS)          // 8192

// Scratch (device globals: allocation-free contract)
__device__ float g_qkv[(size_t)MM * D3];   // [B*S, 3D] : q | k | v
__device__ float g_att[(size_t)MM * DD];   // attention output [B*S, D]

// ---------------------------------------------------------------------------
// SGEMM (NT): C[M,N] = A[M,K] * B[N,K]^T ; A,B row-major, K contiguous.
// 128x128 tile, BK=8, 256 threads, 8x8 microtile.
// ---------------------------------------------------------------------------
__global__ __launch_bounds__(256) void sgemm_nt(const float* __restrict__ A,
                                                const float* __restrict__ B,
                                                float* __restrict__ C,
                                                int M, int N, int K) {
    __shared__ float As[8][128];
    __shared__ float Bs[8][128];

    const int tid = threadIdx.x;
    const int row = tid >> 1;          // 0..127
    const int kc  = (tid & 1) * 4;     // 0 or 4
    const int tx  = tid & 15;
    const int ty  = tid >> 4;

    const float* Ab = A + (size_t)(blockIdx.y * 128 + row) * K + kc;
    const float* Bb = B + (size_t)(blockIdx.x * 128 + row) * K + kc;

    float acc[8][8];
#pragma unroll
    for (int i = 0; i < 8; i++)
#pragma unroll
        for (int j = 0; j < 8; j++) acc[i][j] = 0.0f;

    for (int k0 = 0; k0 < K; k0 += 8) {
        float4 av = *(const float4*)(Ab + k0);
        float4 bv = *(const float4*)(Bb + k0);
        __syncthreads();
        As[kc + 0][row] = av.x; As[kc + 1][row] = av.y;
        As[kc + 2][row] = av.z; As[kc + 3][row] = av.w;
        Bs[kc + 0][row] = bv.x; Bs[kc + 1][row] = bv.y;
        Bs[kc + 2][row] = bv.z; Bs[kc + 3][row] = bv.w;
        __syncthreads();
#pragma unroll
        for (int k = 0; k < 8; k++) {
            float ar[8], br[8];
            *(float4*)&ar[0] = *(const float4*)&As[k][ty * 8];
            *(float4*)&ar[4] = *(const float4*)&As[k][ty * 8 + 4];
            *(float4*)&br[0] = *(const float4*)&Bs[k][tx * 8];
            *(float4*)&br[4] = *(const float4*)&Bs[k][tx * 8 + 4];
#pragma unroll
            for (int i = 0; i < 8; i++)
#pragma unroll
                for (int j = 0; j < 8; j++)
                    acc[i][j] += ar[i] * br[j];
        }
    }

    float* Cb = C + (size_t)(blockIdx.y * 128 + ty * 8) * N + blockIdx.x * 128 + tx * 8;
#pragma unroll
    for (int i = 0; i < 8; i++) {
        *(float4*)&Cb[(size_t)i * N + 0] =
            make_float4(acc[i][0], acc[i][1], acc[i][2], acc[i][3]);
        *(float4*)&Cb[(size_t)i * N + 4] =
            make_float4(acc[i][4], acc[i][5], acc[i][6], acc[i][7]);
    }
}

// ---------------------------------------------------------------------------
// RoPE in-place on q and k slices of g_qkv.
// One thread per (b, s, h, pair j). j in [0,32).
// ---------------------------------------------------------------------------
__global__ __launch_bounds__(256) void rope_kernel(float* __restrict__ qkv,
                                                   const int* __restrict__ pos) {
    int p = blockIdx.x * blockDim.x + threadIdx.x;
    if (p >= BB * SS * HH * (DK / 2)) return;
    int j = p & 31;
    int h = (p >> 5) & (HH - 1);
    int s = (p >> 9) & (SS - 1);
    int b = p >> 20;

    float e   = -(float)(2 * j) / (float)DK;
    float inv = powf(10000.0f, e);
    float ang = (float)pos[s] * inv;
    float sn, cs;
    sincosf(ang, &sn, &cs);

    size_t base = ((size_t)(b * SS + s)) * D3 + h * DK + 2 * j;
    float q1 = qkv[base], q2 = qkv[base + 1];
    qkv[base]     = q1 * cs - q2 * sn;
    qkv[base + 1] = q1 * sn + q2 * cs;
    float k1 = qkv[base + DD], k2 = qkv[base + DD + 1];
    qkv[base + DD]     = k1 * cs - k2 * sn;
    qkv[base + DD + 1] = k1 * sn + k2 * cs;
}

// ---------------------------------------------------------------------------
// Flash attention, causal, fp32.
// Block: (qb, h, b). BQ=128 query rows, K-tiles of 64. 256 threads (16x16),
// each thread owns an 8x4 microtile of S/P and an 8x4 slice of O.
// smem: Qs[64][128] + Ks[64][64] + Vs[64][64] + Ps[128][64] = 96 KB (dynamic).
// ---------------------------------------------------------------------------
__global__ __launch_bounds__(256) void attn_kernel(const float* __restrict__ qkv,
                                                   float* __restrict__ out) {
    extern __shared__ float sm[];
    float* Qs = sm;                        // [64][128]  (dk-major)
    float* Ks = Qs + 64 * 128;             // [64][64]   (dk-major)
    float* Vs = Ks + 64 * 64;              // [64][64]   (seq-major)
    float* Ps = Vs + 64 * 64;              // [128][64]

    const int tid = threadIdx.x;
    const int tx = tid & 15;
    const int ty = tid >> 4;
    const int qb = blockIdx.x;
    const int h  = blockIdx.y;
    const int b  = blockIdx.z;

    // Load Q tile [128 rows][64 dk], store dk-major (transposed)
#pragma unroll
    for (int it = 0; it < 8; it++) {
        int idx = it * 256 + tid;
        int r  = idx >> 4;
        int kq = (idx & 15) << 2;
        const float* src = qkv + ((size_t)(b * SS + qb * 128 + r)) * D3 + h * DK + kq;
        float4 v = *(const float4*)src;
        Qs[(kq + 0) * 128 + r] = v.x;
        Qs[(kq + 1) * 128 + r] = v.y;
        Qs[(kq + 2) * 128 + r] = v.z;
        Qs[(kq + 3) * 128 + r] = v.w;
    }

    float m[8], l[8], o[8][4];
#pragma unroll
    for (int i = 0; i < 8; i++) {
        m[i] = -1e30f;
        l[i] = 0.0f;
#pragma unroll
        for (int j = 0; j < 4; j++) o[i][j] = 0.0f;
    }

    const int nkt = 2 * qb + 2;   // causal: tiles covering cols <= qb*128+127
    for (int kt = 0; kt < nkt; kt++) {
        __syncthreads();   // protect Ks/Vs/Ps against previous iteration readers
        // Load K tile (dk-major) and V tile (seq-major)
#pragma unroll
        for (int it = 0; it < 4; it++) {
            int idx = it * 256 + tid;
            int c  = idx >> 4;
            int kq = (idx & 15) << 2;
            size_t rbase = ((size_t)(b * SS + kt * 64 + c)) * D3 + h * DK + kq;
            float4 kv = *(const float4*)(qkv + rbase + DD);
            Ks[(kq + 0) * 64 + c] = kv.x;
            Ks[(kq + 1) * 64 + c] = kv.y;
            Ks[(kq + 2) * 64 + c] = kv.z;
            Ks[(kq + 3) * 64 + c] = kv.w;
            *(float4*)&Vs[c * 64 + kq] = *(const float4*)(qkv + rbase + 2 * DD);
        }
        __syncthreads();

        // S = Q K^T (8x4 microtile)
        float s[8][4];
#pragma unroll
        for (int i = 0; i < 8; i++)
#pragma unroll
            for (int j = 0; j < 4; j++) s[i][j] = 0.0f;

#pragma unroll 8
        for (int k = 0; k < 64; k++) {
            float qr[8], kr[4];
            *(float4*)&qr[0] = *(const float4*)&Qs[k * 128 + ty * 8];
            *(float4*)&qr[4] = *(const float4*)&Qs[k * 128 + ty * 8 + 4];
            *(float4*)&kr[0] = *(const float4*)&Ks[k * 64 + tx * 4];
#pragma unroll
            for (int i = 0; i < 8; i++)
#pragma unroll
                for (int j = 0; j < 4; j++)
                    s[i][j] += qr[i] * kr[j];
        }

        // scale + causal mask + online softmax update
        const int colbase = kt * 64 + tx * 4;
#pragma unroll
        for (int i = 0; i < 8; i++) {
            const int grow = qb * 128 + ty * 8 + i;
            float rmax = -1e30f;
#pragma unroll
            for (int j = 0; j < 4; j++) {
                float v = s[i][j] * 0.125f;
                if (colbase + j > grow) v = -1e30f;
                s[i][j] = v;
                rmax = fmaxf(rmax, v);
            }
#pragma unroll
            for (int off = 8; off > 0; off >>= 1)
                rmax = fmaxf(rmax, __shfl_xor_sync(0xffffffffu, rmax, off, 16));
            float mnew = fmaxf(m[i], rmax);
            float corr = __expf(m[i] - mnew);
            float psum = 0.0f;
#pragma unroll
            for (int j = 0; j < 4; j++) {
                float pv = __expf(s[i][j] - mnew);
                s[i][j] = pv;
                psum += pv;
            }
#pragma unroll
            for (int off = 8; off > 0; off >>= 1)
                psum += __shfl_xor_sync(0xffffffffu, psum, off, 16);
            l[i] = l[i] * corr + psum;
#pragma unroll
            for (int j = 0; j < 4; j++) o[i][j] *= corr;
            m[i] = mnew;
            *(float4*)&Ps[(ty * 8 + i) * 64 + tx * 4] = *(float4*)&s[i][0];
        }
        __syncthreads();

        // O += P V
#pragma unroll 8
        for (int k = 0; k < 64; k++) {
            float4 vv = *(const float4*)&Vs[k * 64 + tx * 4];
#pragma unroll
            for (int i = 0; i < 8; i++) {
                float pv = Ps[(ty * 8 + i) * 64 + k];
                o[i][0] += pv * vv.x;
                o[i][1] += pv * vv.y;
                o[i][2] += pv * vv.z;
                o[i][3] += pv * vv.w;
            }
        }
    }

    // epilogue: normalize and store in [B*S, D] layout
#pragma unroll
    for (int i = 0; i < 8; i++) {
        float inv = 1.0f / l[i];
        float4 r = make_float4(o[i][0] * inv, o[i][1] * inv,
                               o[i][2] * inv, o[i][3] * inv);
        float* dst = out + ((size_t)(b * SS + qb * 128 + ty * 8 + i)) * DD
                         + h * DK + tx * 4;
        *(float4*)dst = r;
    }
}

// ---------------------------------------------------------------------------
extern "C" void kernel_launch(void* const* d_in, const int* in_sizes, int n_in,
                              void* d_out, int out_size) {
    const float* x    = (const float*)d_in[0];
    const int*   pos  = (const int*)d_in[1];
    const float* Wqkv = (const float*)d_in[2];
    const float* Wo   = (const float*)d_in[3];
    float* out = (float*)d_out;

    float* qkv = nullptr;
    float* att = nullptr;
    cudaGetSymbolAddress((void**)&qkv, g_qkv);
    cudaGetSymbolAddress((void**)&att, g_att);

    // 1) QKV projection: [8192,1024] x [3072,1024]^T
    {
        dim3 grid(D3 / 128, MM / 128);
        sgemm_nt<<<grid, 256>>>(x, Wqkv, qkv, MM, D3, DD);
    }

    // 2) RoPE on q,k in place
    {
        int total = BB * SS * HH * (DK / 2);
        rope_kernel<<<(total + 255) / 256, 256>>>(qkv, pos);
    }

    // 3) Causal flash attention
    {
        static const int smem = (64 * 128 + 64 * 64 + 64 * 64 + 128 * 64) * 4; // 96 KB
        cudaFuncSetAttribute(attn_kernel,
                             cudaFuncAttributeMaxDynamicSharedMemorySize, smem);
        dim3 grid(SS / 128, HH, BB);
        attn_kernel<<<grid, 256, smem>>>(qkv, att);
    }

    // 4) Output projection: [8192,1024] x [1024,1024]^T
    {
        dim3 grid(DD / 128, MM / 128);
        sgemm_nt<<<grid, 256>>>(att, Wo, out, MM, DD, DD);
    }
}

// round 7
// speedup vs baseline: 1.4915x; 1.4915x over previous
#include <cuda_runtime.h>
#include <cuda_bf16.h>
#include <cstdint>
#include <cstdio>

// Problem constants
#define BB 4
#define SS 2048
#define DD 1024
#define HH 16
#define DK 64
#define D3 3072
#define MM (BB*SS)          // 8192

// Scratch (device globals: allocation-free contract)
__device__ float g_qkv[(size_t)MM * D3];   // [B*S, 3D] : q | k | v
__device__ float g_att[(size_t)MM * DD];   // attention output [B*S, D]
__device__ __nv_bfloat16 g_ahi[(size_t)MM * DD];
__device__ __nv_bfloat16 g_alo[(size_t)MM * DD];
__device__ __nv_bfloat16 g_bhi[(size_t)D3 * DD];
__device__ __nv_bfloat16 g_blo[(size_t)D3 * DD];

// ---------------------------------------------------------------------------
// helpers
// ---------------------------------------------------------------------------
__device__ __forceinline__ uint32_t smem_u32(const void* p) {
    uint32_t a;
    asm("{ .reg .u64 t; cvta.to.shared.u64 t, %1; cvt.u32.u64 %0, t; }" : "=r"(a) : "l"(p));
    return a;
}
__device__ __forceinline__ void ldsm4(uint32_t& r0, uint32_t& r1, uint32_t& r2,
                                      uint32_t& r3, uint32_t addr) {
    asm volatile("ldmatrix.sync.aligned.m8n8.x4.shared.b16 {%0,%1,%2,%3}, [%4];"
                 : "=r"(r0), "=r"(r1), "=r"(r2), "=r"(r3) : "r"(addr));
}
__device__ __forceinline__ void mma16816(float* c, const uint32_t* a,
                                         uint32_t b0, uint32_t b1) {
    asm volatile(
        "mma.sync.aligned.m16n8k16.row.col.f32.bf16.bf16.f32 "
        "{%0,%1,%2,%3}, {%4,%5,%6,%7}, {%8,%9}, {%0,%1,%2,%3};"
        : "+f"(c[0]), "+f"(c[1]), "+f"(c[2]), "+f"(c[3])
        : "r"(a[0]), "r"(a[1]), "r"(a[2]), "r"(a[3]), "r"(b0), "r"(b1));
}

// ---------------------------------------------------------------------------
// Split fp32 -> bf16 hi + bf16 lo (2 elements per thread)
// ---------------------------------------------------------------------------
__global__ __launch_bounds__(256) void split_bf16(const float2* __restrict__ x,
                                                  __nv_bfloat162* __restrict__ hi,
                                                  __nv_bfloat162* __restrict__ lo,
                                                  int n2) {
    int i = blockIdx.x * blockDim.x + threadIdx.x;
    if (i >= n2) return;
    float2 v = x[i];
    __nv_bfloat16 hx = __float2bfloat16(v.x);
    __nv_bfloat16 hy = __float2bfloat16(v.y);
    float rx = v.x - __bfloat162float(hx);
    float ry = v.y - __bfloat162float(hy);
    __nv_bfloat162 h; h.x = hx; h.y = hy;
    hi[i] = h;
    lo[i] = __floats2bfloat162_rn(rx, ry);
}

// ---------------------------------------------------------------------------
// Warp-MMA bf16 split-2 GEMM (NT): C[M,N] = A[M,K]*B[N,K]^T, fp32 out.
// CTA tile 128x128, KBLK=64. 8 warps: 2(M) x 4(N), warp tile 64x32.
// smem rows padded to 72 bf16 (144 B) -> conflict-free ldmatrix.
// C += Ahi Bhi^T + Ahi Blo^T + Alo Bhi^T
//
// ldmatrix.x4 register mapping (given our lane addressing):
//   r0 = rows 0-7  / k 0-7     r1 = rows 8-15 / k 0-7
//   r2 = rows 0-7  / k 8-15    r3 = rows 8-15 / k 8-15
// A fragment = (r0,r1,r2,r3) directly.
// B n8-tile fragment = (r_lo, r_lo+2) where lo = (nt>>1)*4 + (nt&1).
// ---------------------------------------------------------------------------
#define RS 72                       // bf16 per smem row (64 + 8 pad)
#define TILE_SMB (128 * RS * 2)     // 18432 B per tile
#define GEMM_SMEM (4 * TILE_SMB)    // 73728 B

__global__ __launch_bounds__(256) void gemm_mma(
    const __nv_bfloat16* __restrict__ Ahi, const __nv_bfloat16* __restrict__ Alo,
    const __nv_bfloat16* __restrict__ Bhi, const __nv_bfloat16* __restrict__ Blo,
    float* __restrict__ C, int N, int K)
{
    extern __shared__ __align__(16) __nv_bfloat16 sm[];
    __nv_bfloat16* tile[4] = { sm, sm + 128 * RS, sm + 2 * 128 * RS, sm + 3 * 128 * RS };

    const int tid  = threadIdx.x;
    const int lane = tid & 31;
    const int wid  = tid >> 5;
    const int wm   = wid & 1;        // 0..1 -> 64-row slab
    const int wn   = wid >> 1;       // 0..3 -> 32-col slab
    const int m0 = blockIdx.y * 128;
    const int n0 = blockIdx.x * 128;

    const __nv_bfloat16* srcs[4] = { Ahi + (size_t)m0 * K, Alo + (size_t)m0 * K,
                                     Bhi + (size_t)n0 * K, Blo + (size_t)n0 * K };

    // ldmatrix lane address components
    const int lrow  = (lane & 7) + ((lane >> 3) & 1) * 8;  // 0..15
    const int lkadd = (lane >> 4) * 8;                     // 0 or 8

    const uint32_t smb = smem_u32(sm);
    const uint32_t aBaseHi = smb + (uint32_t)((wm * 64 + lrow) * RS + lkadd) * 2;
    const uint32_t aBaseLo = aBaseHi + TILE_SMB;
    const uint32_t bBaseHi = smb + 2 * TILE_SMB +
                             (uint32_t)((wn * 32 + lrow) * RS + lkadd) * 2;
    const uint32_t bBaseLo = bBaseHi + TILE_SMB;

    float acc[4][4][4];
#pragma unroll
    for (int i = 0; i < 4; i++)
#pragma unroll
        for (int j = 0; j < 4; j++)
#pragma unroll
            for (int r = 0; r < 4; r++) acc[i][j][r] = 0.0f;

    const int nStages = K >> 6;
    for (int s = 0; s < nStages; s++) {
        const int k0 = s << 6;
        // stage load: 4 tiles of [128 x 64] bf16
        __syncthreads();
#pragma unroll
        for (int t = 0; t < 4; t++) {
            const __nv_bfloat16* src = srcs[t] + k0;
#pragma unroll
            for (int it = 0; it < 4; it++) {
                int q = it * 256 + tid;          // 0..1023 16B-chunks
                int r = q >> 3;
                int c = q & 7;
                *(uint4*)(tile[t] + r * RS + c * 8) =
                    *(const uint4*)(src + (size_t)r * K + c * 8);
            }
        }
        __syncthreads();

#pragma unroll
        for (int ks = 0; ks < 4; ks++) {
            const uint32_t kb = (uint32_t)(ks * 16 * 2);   // byte offset along k
            // B fragments: hi & lo, n-tiles 0-1 from first x4, 2-3 from second
            uint32_t bH[8], bL[8];
            ldsm4(bH[0], bH[1], bH[2], bH[3], bBaseHi + kb);
            ldsm4(bH[4], bH[5], bH[6], bH[7], bBaseHi + kb + 16 * RS * 2);
            ldsm4(bL[0], bL[1], bL[2], bL[3], bBaseLo + kb);
            ldsm4(bL[4], bL[5], bL[6], bL[7], bBaseLo + kb + 16 * RS * 2);
#pragma unroll
            for (int mt = 0; mt < 4; mt++) {
                uint32_t aH[4], aL[4];
                const uint32_t moff = (uint32_t)(mt * 16 * RS * 2);
                ldsm4(aH[0], aH[1], aH[2], aH[3], aBaseHi + moff + kb);
                ldsm4(aL[0], aL[1], aL[2], aL[3], aBaseLo + moff + kb);
#pragma unroll
                for (int nt = 0; nt < 4; nt++) {
                    const int lo = ((nt >> 1) << 2) + (nt & 1);
                    mma16816(acc[mt][nt], aH, bH[lo], bH[lo + 2]);
                    mma16816(acc[mt][nt], aH, bL[lo], bL[lo + 2]);
                    mma16816(acc[mt][nt], aL, bH[lo], bH[lo + 2]);
                }
            }
        }
    }

    // epilogue: direct float2 stores
    const int qrow = lane >> 2;
    const int qcol = (lane & 3) * 2;
#pragma unroll
    for (int mt = 0; mt < 4; mt++) {
#pragma unroll
        for (int nt = 0; nt < 4; nt++) {
            float* base = C + (size_t)(m0 + wm * 64 + mt * 16 + qrow) * N
                            + n0 + wn * 32 + nt * 8 + qcol;
            *(float2*)base = make_float2(acc[mt][nt][0], acc[mt][nt][1]);
            *(float2*)(base + (size_t)8 * N) = make_float2(acc[mt][nt][2], acc[mt][nt][3]);
        }
    }
}

// ---------------------------------------------------------------------------
// RoPE in-place on q and k slices of g_qkv.
// ---------------------------------------------------------------------------
__global__ __launch_bounds__(256) void rope_kernel(float* __restrict__ qkv,
                                                   const int* __restrict__ pos) {
    int p = blockIdx.x * blockDim.x + threadIdx.x;
    if (p >= BB * SS * HH * (DK / 2)) return;
    int j = p & 31;
    int h = (p >> 5) & (HH - 1);
    int s = (p >> 9) & (SS - 1);
    int b = p >> 20;

    float e   = -(float)(2 * j) / (float)DK;
    float inv = powf(10000.0f, e);
    float ang = (float)pos[s] * inv;
    float sn, cs;
    sincosf(ang, &sn, &cs);

    size_t base = ((size_t)(b * SS + s)) * D3 + h * DK + 2 * j;
    float q1 = qkv[base], q2 = qkv[base + 1];
    qkv[base]     = q1 * cs - q2 * sn;
    qkv[base + 1] = q1 * sn + q2 * cs;
    float k1 = qkv[base + DD], k2 = qkv[base + DD + 1];
    qkv[base + DD]     = k1 * cs - k2 * sn;
    qkv[base + DD + 1] = k1 * sn + k2 * cs;
}

// ---------------------------------------------------------------------------
// Flash attention, causal, fp32 (unchanged from passing version).
// ---------------------------------------------------------------------------
__global__ __launch_bounds__(256) void attn_kernel(const float* __restrict__ qkv,
                                                   float* __restrict__ out) {
    extern __shared__ float smf[];
    float* Qs = smf;                       // [64][128]  (dk-major)
    float* Ks = Qs + 64 * 128;             // [64][64]   (dk-major)
    float* Vs = Ks + 64 * 64;              // [64][64]   (seq-major)
    float* Ps = Vs + 64 * 64;              // [128][64]

    const int tid = threadIdx.x;
    const int tx = tid & 15;
    const int ty = tid >> 4;
    const int qb = blockIdx.x;
    const int h  = blockIdx.y;
    const int b  = blockIdx.z;

#pragma unroll
    for (int it = 0; it < 8; it++) {
        int idx = it * 256 + tid;
        int r  = idx >> 4;
        int kq = (idx & 15) << 2;
        const float* src = qkv + ((size_t)(b * SS + qb * 128 + r)) * D3 + h * DK + kq;
        float4 v = *(const float4*)src;
        Qs[(kq + 0) * 128 + r] = v.x;
        Qs[(kq + 1) * 128 + r] = v.y;
        Qs[(kq + 2) * 128 + r] = v.z;
        Qs[(kq + 3) * 128 + r] = v.w;
    }

    float m[8], l[8], o[8][4];
#pragma unroll
    for (int i = 0; i < 8; i++) {
        m[i] = -1e30f;
        l[i] = 0.0f;
#pragma unroll
        for (int j = 0; j < 4; j++) o[i][j] = 0.0f;
    }

    const int nkt = 2 * qb + 2;
    for (int kt = 0; kt < nkt; kt++) {
        __syncthreads();
#pragma unroll
        for (int it = 0; it < 4; it++) {
            int idx = it * 256 + tid;
            int c  = idx >> 4;
            int kq = (idx & 15) << 2;
            size_t rbase = ((size_t)(b * SS + kt * 64 + c)) * D3 + h * DK + kq;
            float4 kv = *(const float4*)(qkv + rbase + DD);
            Ks[(kq + 0) * 64 + c] = kv.x;
            Ks[(kq + 1) * 64 + c] = kv.y;
            Ks[(kq + 2) * 64 + c] = kv.z;
            Ks[(kq + 3) * 64 + c] = kv.w;
            *(float4*)&Vs[c * 64 + kq] = *(const float4*)(qkv + rbase + 2 * DD);
        }
        __syncthreads();

        float s[8][4];
#pragma unroll
        for (int i = 0; i < 8; i++)
#pragma unroll
            for (int j = 0; j < 4; j++) s[i][j] = 0.0f;

#pragma unroll 8
        for (int k = 0; k < 64; k++) {
            float qr[8], kr[4];
            *(float4*)&qr[0] = *(const float4*)&Qs[k * 128 + ty * 8];
            *(float4*)&qr[4] = *(const float4*)&Qs[k * 128 + ty * 8 + 4];
            *(float4*)&kr[0] = *(const float4*)&Ks[k * 64 + tx * 4];
#pragma unroll
            for (int i = 0; i < 8; i++)
#pragma unroll
                for (int j = 0; j < 4; j++)
                    s[i][j] += qr[i] * kr[j];
        }

        const int colbase = kt * 64 + tx * 4;
#pragma unroll
        for (int i = 0; i < 8; i++) {
            const int grow = qb * 128 + ty * 8 + i;
            float rmax = -1e30f;
#pragma unroll
            for (int j = 0; j < 4; j++) {
                float v = s[i][j] * 0.125f;
                if (colbase + j > grow) v = -1e30f;
                s[i][j] = v;
                rmax = fmaxf(rmax, v);
            }
#pragma unroll
            for (int off = 8; off > 0; off >>= 1)
                rmax = fmaxf(rmax, __shfl_xor_sync(0xffffffffu, rmax, off, 16));
            float mnew = fmaxf(m[i], rmax);
            float corr = __expf(m[i] - mnew);
            float psum = 0.0f;
#pragma unroll
            for (int j = 0; j < 4; j++) {
                float pv = __expf(s[i][j] - mnew);
                s[i][j] = pv;
                psum += pv;
            }
#pragma unroll
            for (int off = 8; off > 0; off >>= 1)
                psum += __shfl_xor_sync(0xffffffffu, psum, off, 16);
            l[i] = l[i] * corr + psum;
#pragma unroll
            for (int j = 0; j < 4; j++) o[i][j] *= corr;
            m[i] = mnew;
            *(float4*)&Ps[(ty * 8 + i) * 64 + tx * 4] = *(float4*)&s[i][0];
        }
        __syncthreads();

#pragma unroll 8
        for (int k = 0; k < 64; k++) {
            float4 vv = *(const float4*)&Vs[k * 64 + tx * 4];
#pragma unroll
            for (int i = 0; i < 8; i++) {
                float pv = Ps[(ty * 8 + i) * 64 + k];
                o[i][0] += pv * vv.x;
                o[i][1] += pv * vv.y;
                o[i][2] += pv * vv.z;
                o[i][3] += pv * vv.w;
            }
        }
    }

#pragma unroll
    for (int i = 0; i < 8; i++) {
        float inv = 1.0f / l[i];
        float4 r = make_float4(o[i][0] * inv, o[i][1] * inv,
                               o[i][2] * inv, o[i][3] * inv);
        float* dst = out + ((size_t)(b * SS + qb * 128 + ty * 8 + i)) * DD
                         + h * DK + tx * 4;
        *(float4*)dst = r;
    }
}

// ---------------------------------------------------------------------------
extern "C" void kernel_launch(void* const* d_in, const int* in_sizes, int n_in,
                              void* d_out, int out_size) {
    const float* x    = (const float*)d_in[0];
    const int*   pos  = (const int*)d_in[1];
    const float* Wqkv = (const float*)d_in[2];
    const float* Wo   = (const float*)d_in[3];
    float* out = (float*)d_out;

    float *qkv = nullptr, *att = nullptr;
    __nv_bfloat16 *ahi = nullptr, *alo = nullptr, *bhi = nullptr, *blo = nullptr;
    cudaGetSymbolAddress((void**)&qkv, g_qkv);
    cudaGetSymbolAddress((void**)&att, g_att);
    cudaGetSymbolAddress((void**)&ahi, g_ahi);
    cudaGetSymbolAddress((void**)&alo, g_alo);
    cudaGetSymbolAddress((void**)&bhi, g_bhi);
    cudaGetSymbolAddress((void**)&blo, g_blo);

    cudaFuncSetAttribute(gemm_mma, cudaFuncAttributeMaxDynamicSharedMemorySize, GEMM_SMEM);

    // 1) split x and Wqkv to bf16 hi/lo
    {
        int n2 = MM * DD / 2;
        split_bf16<<<(n2 + 255) / 256, 256>>>((const float2*)x,
            (__nv_bfloat162*)ahi, (__nv_bfloat162*)alo, n2);
        int w2 = D3 * DD / 2;
        split_bf16<<<(w2 + 255) / 256, 256>>>((const float2*)Wqkv,
            (__nv_bfloat162*)bhi, (__nv_bfloat162*)blo, w2);
    }

    // 2) QKV projection (tensor cores via mma.sync): [8192,1024] x [3072,1024]^T
    {
        dim3 grid(D3 / 128, MM / 128);
        gemm_mma<<<grid, 256, GEMM_SMEM>>>(ahi, alo, bhi, blo, qkv, D3, DD);
    }

    // 3) RoPE on q,k in place
    {
        int total = BB * SS * HH * (DK / 2);
        rope_kernel<<<(total + 255) / 256, 256>>>(qkv, pos);
    }

    // 4) Causal flash attention
    {
        static const int smem = (64 * 128 + 64 * 64 + 64 * 64 + 128 * 64) * 4; // 96 KB
        cudaFuncSetAttribute(attn_kernel,
                             cudaFuncAttributeMaxDynamicSharedMemorySize, smem);
        dim3 grid(SS / 128, HH, BB);
        attn_kernel<<<grid, 256, smem>>>(qkv, att);
    }

    // 5) split att and Wo, then output projection
    {
        int n2 = MM * DD / 2;
        split_bf16<<<(n2 + 255) / 256, 256>>>((const float2*)att,
            (__nv_bfloat162*)ahi, (__nv_bfloat162*)alo, n2);
        int w2 = DD * DD / 2;
        split_bf16<<<(w2 + 255) / 256, 256>>>((const float2*)Wo,
            (__nv_bfloat162*)bhi, (__nv_bfloat162*)blo, w2);
        dim3 grid(DD / 128, MM / 128);
        gemm_mma<<<grid, 256, GEMM_SMEM>>>(ahi, alo, bhi, blo, out, DD, DD);
    }
}

// round 8
// speedup vs baseline: 2.0001x; 1.3410x over previous
#include <cuda_runtime.h>
#include <cuda_bf16.h>
#include <cstdint>
#include <cstdio>

// Problem constants
#define BB 4
#define SS 2048
#define DD 1024
#define HH 16
#define DK 64
#define D3 3072
#define MM (BB*SS)          // 8192

// Scratch (device globals: allocation-free contract)
__device__ float g_qkv[(size_t)MM * D3];   // [B*S, 3D] : q | k | v
__device__ float g_att[(size_t)MM * DD];   // attention output [B*S, D]
__device__ __nv_bfloat16 g_ahi[(size_t)MM * DD];
__device__ __nv_bfloat16 g_alo[(size_t)MM * DD];
__device__ __nv_bfloat16 g_bhi[(size_t)D3 * DD];
__device__ __nv_bfloat16 g_blo[(size_t)D3 * DD];

// ---------------------------------------------------------------------------
// helpers
// ---------------------------------------------------------------------------
__device__ __forceinline__ uint32_t smem_u32(const void* p) {
    uint32_t a;
    asm("{ .reg .u64 t; cvta.to.shared.u64 t, %1; cvt.u32.u64 %0, t; }" : "=r"(a) : "l"(p));
    return a;
}
__device__ __forceinline__ void ldsm4(uint32_t& r0, uint32_t& r1, uint32_t& r2,
                                      uint32_t& r3, uint32_t addr) {
    asm volatile("ldmatrix.sync.aligned.m8n8.x4.shared.b16 {%0,%1,%2,%3}, [%4];"
                 : "=r"(r0), "=r"(r1), "=r"(r2), "=r"(r3) : "r"(addr));
}
__device__ __forceinline__ void mma16816(float* c, const uint32_t* a,
                                         uint32_t b0, uint32_t b1) {
    asm volatile(
        "mma.sync.aligned.m16n8k16.row.col.f32.bf16.bf16.f32 "
        "{%0,%1,%2,%3}, {%4,%5,%6,%7}, {%8,%9}, {%0,%1,%2,%3};"
        : "+f"(c[0]), "+f"(c[1]), "+f"(c[2]), "+f"(c[3])
        : "r"(a[0]), "r"(a[1]), "r"(a[2]), "r"(a[3]), "r"(b0), "r"(b1));
}
__device__ __forceinline__ uint32_t pack_bf2(float a, float b) {
    __nv_bfloat162 t = __floats2bfloat162_rn(a, b);   // .x = a in low bits
    return *(uint32_t*)&t;
}

// ---------------------------------------------------------------------------
// Split fp32 -> bf16 hi + bf16 lo (2 elements per thread)
// ---------------------------------------------------------------------------
__global__ __launch_bounds__(256) void split_bf16(const float2* __restrict__ x,
                                                  __nv_bfloat162* __restrict__ hi,
                                                  __nv_bfloat162* __restrict__ lo,
                                                  int n2) {
    int i = blockIdx.x * blockDim.x + threadIdx.x;
    if (i >= n2) return;
    float2 v = x[i];
    __nv_bfloat16 hx = __float2bfloat16(v.x);
    __nv_bfloat16 hy = __float2bfloat16(v.y);
    float rx = v.x - __bfloat162float(hx);
    float ry = v.y - __bfloat162float(hy);
    __nv_bfloat162 h; h.x = hx; h.y = hy;
    hi[i] = h;
    lo[i] = __floats2bfloat162_rn(rx, ry);
}

// ---------------------------------------------------------------------------
// Warp-MMA bf16 split-2 GEMM (NT): unchanged from passing R6 kernel.
// ---------------------------------------------------------------------------
#define RS 72                       // bf16 per smem row (64 + 8 pad)
#define TILE_SMB (128 * RS * 2)     // 18432 B per tile
#define GEMM_SMEM (4 * TILE_SMB)    // 73728 B

__global__ __launch_bounds__(256) void gemm_mma(
    const __nv_bfloat16* __restrict__ Ahi, const __nv_bfloat16* __restrict__ Alo,
    const __nv_bfloat16* __restrict__ Bhi, const __nv_bfloat16* __restrict__ Blo,
    float* __restrict__ C, int N, int K)
{
    extern __shared__ __align__(16) __nv_bfloat16 sm[];
    __nv_bfloat16* tile[4] = { sm, sm + 128 * RS, sm + 2 * 128 * RS, sm + 3 * 128 * RS };

    const int tid  = threadIdx.x;
    const int lane = tid & 31;
    const int wid  = tid >> 5;
    const int wm   = wid & 1;
    const int wn   = wid >> 1;
    const int m0 = blockIdx.y * 128;
    const int n0 = blockIdx.x * 128;

    const __nv_bfloat16* srcs[4] = { Ahi + (size_t)m0 * K, Alo + (size_t)m0 * K,
                                     Bhi + (size_t)n0 * K, Blo + (size_t)n0 * K };

    const int lrow  = (lane & 7) + ((lane >> 3) & 1) * 8;
    const int lkadd = (lane >> 4) * 8;

    const uint32_t smb = smem_u32(sm);
    const uint32_t aBaseHi = smb + (uint32_t)((wm * 64 + lrow) * RS + lkadd) * 2;
    const uint32_t aBaseLo = aBaseHi + TILE_SMB;
    const uint32_t bBaseHi = smb + 2 * TILE_SMB +
                             (uint32_t)((wn * 32 + lrow) * RS + lkadd) * 2;
    const uint32_t bBaseLo = bBaseHi + TILE_SMB;

    float acc[4][4][4];
#pragma unroll
    for (int i = 0; i < 4; i++)
#pragma unroll
        for (int j = 0; j < 4; j++)
#pragma unroll
            for (int r = 0; r < 4; r++) acc[i][j][r] = 0.0f;

    const int nStages = K >> 6;
    for (int s = 0; s < nStages; s++) {
        const int k0 = s << 6;
        __syncthreads();
#pragma unroll
        for (int t = 0; t < 4; t++) {
            const __nv_bfloat16* src = srcs[t] + k0;
#pragma unroll
            for (int it = 0; it < 4; it++) {
                int q = it * 256 + tid;
                int r = q >> 3;
                int c = q & 7;
                *(uint4*)(tile[t] + r * RS + c * 8) =
                    *(const uint4*)(src + (size_t)r * K + c * 8);
            }
        }
        __syncthreads();

#pragma unroll
        for (int ks = 0; ks < 4; ks++) {
            const uint32_t kb = (uint32_t)(ks * 16 * 2);
            uint32_t bH[8], bL[8];
            ldsm4(bH[0], bH[1], bH[2], bH[3], bBaseHi + kb);
            ldsm4(bH[4], bH[5], bH[6], bH[7], bBaseHi + kb + 16 * RS * 2);
            ldsm4(bL[0], bL[1], bL[2], bL[3], bBaseLo + kb);
            ldsm4(bL[4], bL[5], bL[6], bL[7], bBaseLo + kb + 16 * RS * 2);
#pragma unroll
            for (int mt = 0; mt < 4; mt++) {
                uint32_t aH[4], aL[4];
                const uint32_t moff = (uint32_t)(mt * 16 * RS * 2);
                ldsm4(aH[0], aH[1], aH[2], aH[3], aBaseHi + moff + kb);
                ldsm4(aL[0], aL[1], aL[2], aL[3], aBaseLo + moff + kb);
#pragma unroll
                for (int nt = 0; nt < 4; nt++) {
                    const int lo = ((nt >> 1) << 2) + (nt & 1);
                    mma16816(acc[mt][nt], aH, bH[lo], bH[lo + 2]);
                    mma16816(acc[mt][nt], aH, bL[lo], bL[lo + 2]);
                    mma16816(acc[mt][nt], aL, bH[lo], bH[lo + 2]);
                }
            }
        }
    }

    const int qrow = lane >> 2;
    const int qcol = (lane & 3) * 2;
#pragma unroll
    for (int mt = 0; mt < 4; mt++) {
#pragma unroll
        for (int nt = 0; nt < 4; nt++) {
            float* base = C + (size_t)(m0 + wm * 64 + mt * 16 + qrow) * N
                            + n0 + wn * 32 + nt * 8 + qcol;
            *(float2*)base = make_float2(acc[mt][nt][0], acc[mt][nt][1]);
            *(float2*)(base + (size_t)8 * N) = make_float2(acc[mt][nt][2], acc[mt][nt][3]);
        }
    }
}

// ---------------------------------------------------------------------------
// RoPE in-place on q and k slices of g_qkv (unchanged).
// ---------------------------------------------------------------------------
__global__ __launch_bounds__(256) void rope_kernel(float* __restrict__ qkv,
                                                   const int* __restrict__ pos) {
    int p = blockIdx.x * blockDim.x + threadIdx.x;
    if (p >= BB * SS * HH * (DK / 2)) return;
    int j = p & 31;
    int h = (p >> 5) & (HH - 1);
    int s = (p >> 9) & (SS - 1);
    int b = p >> 20;

    float e   = -(float)(2 * j) / (float)DK;
    float inv = powf(10000.0f, e);
    float ang = (float)pos[s] * inv;
    float sn, cs;
    sincosf(ang, &sn, &cs);

    size_t base = ((size_t)(b * SS + s)) * D3 + h * DK + 2 * j;
    float q1 = qkv[base], q2 = qkv[base + 1];
    qkv[base]     = q1 * cs - q2 * sn;
    qkv[base + 1] = q1 * sn + q2 * cs;
    float k1 = qkv[base + DD], k2 = qkv[base + DD + 1];
    qkv[base + DD]     = k1 * cs - k2 * sn;
    qkv[base + DD + 1] = k1 * sn + k2 * cs;
}

// ---------------------------------------------------------------------------
// Tensor-core causal flash attention (split-2 bf16, fp32 softmax).
// Grid (qb=16, h=16, b=4), 256 threads = 8 warps x 16 q-rows.
// KV tile = 64 keys. Scale 1/8 folded into Q at load.
// smem: Qhi/Qlo [128][72] + Khi/Klo [64][72] + Vthi/Vtlo [64][72] = 73728 B
// ---------------------------------------------------------------------------
#define ARS 72
#define QT_ELE (128 * ARS)
#define KT_ELE (64 * ARS)
#define ATTN_SMEM ((2 * QT_ELE + 4 * KT_ELE) * 2)

__global__ __launch_bounds__(256) void attn_mma(const float* __restrict__ qkv,
                                                float* __restrict__ out) {
    extern __shared__ __align__(16) __nv_bfloat16 as_[];
    __nv_bfloat16* Qhi = as_;
    __nv_bfloat16* Qlo = Qhi + QT_ELE;
    __nv_bfloat16* Khi = Qlo + QT_ELE;
    __nv_bfloat16* Klo = Khi + KT_ELE;
    __nv_bfloat16* Vth = Klo + KT_ELE;
    __nv_bfloat16* Vtl = Vth + KT_ELE;

    const int tid  = threadIdx.x;
    const int lane = tid & 31;
    const int wid  = tid >> 5;
    const int qb = blockIdx.x;
    const int h  = blockIdx.y;
    const int b  = blockIdx.z;

    // ---- load Q (scaled by 1/8), split to hi/lo ----
#pragma unroll
    for (int it = 0; it < 8; it++) {
        int idx = it * 256 + tid;           // 0..2047 float4 units
        int r = idx >> 4;
        int c = (idx & 15) * 4;
        const float* src = qkv + ((size_t)(b * SS + qb * 128 + r)) * D3 + h * DK + c;
        float4 v = *(const float4*)src;
        float f[4] = { v.x * 0.125f, v.y * 0.125f, v.z * 0.125f, v.w * 0.125f };
        __nv_bfloat16 hh[4];
        float ll[4];
#pragma unroll
        for (int i = 0; i < 4; i++) { hh[i] = __float2bfloat16(f[i]);
                                      ll[i] = f[i] - __bfloat162float(hh[i]); }
        __nv_bfloat162 p0; p0.x = hh[0]; p0.y = hh[1];
        __nv_bfloat162 p1; p1.x = hh[2]; p1.y = hh[3];
        *(__nv_bfloat162*)(Qhi + r * ARS + c)     = p0;
        *(__nv_bfloat162*)(Qhi + r * ARS + c + 2) = p1;
        *(__nv_bfloat162*)(Qlo + r * ARS + c)     = __floats2bfloat162_rn(ll[0], ll[1]);
        *(__nv_bfloat162*)(Qlo + r * ARS + c + 2) = __floats2bfloat162_rn(ll[2], ll[3]);
    }
    __syncthreads();

    // ---- Q fragments (held in registers for the whole kernel) ----
    const int lrow  = (lane & 7) + ((lane >> 3) & 1) * 8;
    const int lkadd = (lane >> 4) * 8;
    const uint32_t qBaseHi = smem_u32(Qhi) + (uint32_t)((wid * 16 + lrow) * ARS + lkadd) * 2;
    const uint32_t qBaseLo = smem_u32(Qlo) + (uint32_t)((wid * 16 + lrow) * ARS + lkadd) * 2;
    uint32_t qh[4][4], ql[4][4];
#pragma unroll
    for (int kc = 0; kc < 4; kc++) {
        ldsm4(qh[kc][0], qh[kc][1], qh[kc][2], qh[kc][3], qBaseHi + kc * 32);
        ldsm4(ql[kc][0], ql[kc][1], ql[kc][2], ql[kc][3], qBaseLo + kc * 32);
    }

    const uint32_t kBaseHi = smem_u32(Khi) + (uint32_t)(lrow * ARS + lkadd) * 2;
    const uint32_t kBaseLo = smem_u32(Klo) + (uint32_t)(lrow * ARS + lkadd) * 2;
    const uint32_t vBaseHi = smem_u32(Vth) + (uint32_t)(lrow * ARS + lkadd) * 2;
    const uint32_t vBaseLo = smem_u32(Vtl) + (uint32_t)(lrow * ARS + lkadd) * 2;

    float oacc[8][4];
#pragma unroll
    for (int nt = 0; nt < 8; nt++)
#pragma unroll
        for (int r = 0; r < 4; r++) oacc[nt][r] = 0.0f;
    float m0 = -1e30f, m1 = -1e30f, l0 = 0.0f, l1 = 0.0f;

    const int grow0 = qb * 128 + wid * 16 + (lane >> 2);
    const int grow1 = grow0 + 8;
    const int nkt = 2 * qb + 2;

    for (int kt = 0; kt < nkt; kt++) {
        __syncthreads();
        // ---- load K tile (split), V tile (transposed + split) ----
#pragma unroll
        for (int it = 0; it < 4; it++) {
            int idx = it * 256 + tid;        // 0..1023 float4 units
            int r = idx >> 4;
            int c = (idx & 15) * 4;
            size_t rbase = ((size_t)(b * SS + kt * 64 + r)) * D3 + h * DK;
            float4 kv = *(const float4*)(qkv + rbase + DD + c);
            float kf[4] = { kv.x, kv.y, kv.z, kv.w };
            __nv_bfloat16 khh[4]; float kll[4];
#pragma unroll
            for (int i = 0; i < 4; i++) { khh[i] = __float2bfloat16(kf[i]);
                                          kll[i] = kf[i] - __bfloat162float(khh[i]); }
            __nv_bfloat162 k0p; k0p.x = khh[0]; k0p.y = khh[1];
            __nv_bfloat162 k1p; k1p.x = khh[2]; k1p.y = khh[3];
            *(__nv_bfloat162*)(Khi + r * ARS + c)     = k0p;
            *(__nv_bfloat162*)(Khi + r * ARS + c + 2) = k1p;
            *(__nv_bfloat162*)(Klo + r * ARS + c)     = __floats2bfloat162_rn(kll[0], kll[1]);
            *(__nv_bfloat162*)(Klo + r * ARS + c + 2) = __floats2bfloat162_rn(kll[2], kll[3]);

            float4 vv = *(const float4*)(qkv + rbase + 2 * DD + c);
            float vf[4] = { vv.x, vv.y, vv.z, vv.w };
#pragma unroll
            for (int i = 0; i < 4; i++) {
                __nv_bfloat16 vh = __float2bfloat16(vf[i]);
                Vth[(c + i) * ARS + r] = vh;
                Vtl[(c + i) * ARS + r] = __float2bfloat16(vf[i] - __bfloat162float(vh));
            }
        }
        __syncthreads();

        // ---- S = Q K^T (split-2, 3 passes) ----
        float sacc[8][4];
#pragma unroll
        for (int nt = 0; nt < 8; nt++)
#pragma unroll
            for (int r = 0; r < 4; r++) sacc[nt][r] = 0.0f;

#pragma unroll
        for (int kc = 0; kc < 4; kc++) {
            const uint32_t kb = (uint32_t)(kc * 32);
            uint32_t bH[16], bL[16];
#pragma unroll
            for (int lb = 0; lb < 4; lb++) {
                ldsm4(bH[lb * 4 + 0], bH[lb * 4 + 1], bH[lb * 4 + 2], bH[lb * 4 + 3],
                      kBaseHi + kb + (uint32_t)(lb * 16 * ARS * 2));
                ldsm4(bL[lb * 4 + 0], bL[lb * 4 + 1], bL[lb * 4 + 2], bL[lb * 4 + 3],
                      kBaseLo + kb + (uint32_t)(lb * 16 * ARS * 2));
            }
#pragma unroll
            for (int nt = 0; nt < 8; nt++) {
                const int lo = ((nt >> 1) << 2) + (nt & 1);
                mma16816(sacc[nt], qh[kc], bH[lo], bH[lo + 2]);
                mma16816(sacc[nt], qh[kc], bL[lo], bL[lo + 2]);
                mma16816(sacc[nt], ql[kc], bH[lo], bH[lo + 2]);
            }
        }

        // ---- causal mask ----
        if (kt * 64 + 63 > qb * 128 + wid * 16) {
#pragma unroll
            for (int nt = 0; nt < 8; nt++) {
                int col = kt * 64 + nt * 8 + (lane & 3) * 2;
                if (col > grow0)     sacc[nt][0] = -1e30f;
                if (col + 1 > grow0) sacc[nt][1] = -1e30f;
                if (col > grow1)     sacc[nt][2] = -1e30f;
                if (col + 1 > grow1) sacc[nt][3] = -1e30f;
            }
        }

        // ---- online softmax ----
        float mx0 = -1e30f, mx1 = -1e30f;
#pragma unroll
        for (int nt = 0; nt < 8; nt++) {
            mx0 = fmaxf(mx0, fmaxf(sacc[nt][0], sacc[nt][1]));
            mx1 = fmaxf(mx1, fmaxf(sacc[nt][2], sacc[nt][3]));
        }
        mx0 = fmaxf(mx0, __shfl_xor_sync(0xffffffffu, mx0, 1));
        mx0 = fmaxf(mx0, __shfl_xor_sync(0xffffffffu, mx0, 2));
        mx1 = fmaxf(mx1, __shfl_xor_sync(0xffffffffu, mx1, 1));
        mx1 = fmaxf(mx1, __shfl_xor_sync(0xffffffffu, mx1, 2));
        float mn0 = fmaxf(m0, mx0), mn1 = fmaxf(m1, mx1);
        float cr0 = __expf(m0 - mn0), cr1 = __expf(m1 - mn1);
        float ps0 = 0.0f, ps1 = 0.0f;
#pragma unroll
        for (int nt = 0; nt < 8; nt++) {
            sacc[nt][0] = __expf(sacc[nt][0] - mn0);
            sacc[nt][1] = __expf(sacc[nt][1] - mn0);
            sacc[nt][2] = __expf(sacc[nt][2] - mn1);
            sacc[nt][3] = __expf(sacc[nt][3] - mn1);
            ps0 += sacc[nt][0] + sacc[nt][1];
            ps1 += sacc[nt][2] + sacc[nt][3];
        }
        ps0 += __shfl_xor_sync(0xffffffffu, ps0, 1);
        ps0 += __shfl_xor_sync(0xffffffffu, ps0, 2);
        ps1 += __shfl_xor_sync(0xffffffffu, ps1, 1);
        ps1 += __shfl_xor_sync(0xffffffffu, ps1, 2);
        l0 = l0 * cr0 + ps0;
        l1 = l1 * cr1 + ps1;
        m0 = mn0; m1 = mn1;
#pragma unroll
        for (int nt = 0; nt < 8; nt++) {
            oacc[nt][0] *= cr0; oacc[nt][1] *= cr0;
            oacc[nt][2] *= cr1; oacc[nt][3] *= cr1;
        }

        // ---- O += P V (split-2, 3 passes) ----
#pragma unroll
        for (int kc = 0; kc < 4; kc++) {
            // P fragments from sacc (C-frag -> A-frag repack), hi/lo split
            float f00 = sacc[2*kc][0],   f01 = sacc[2*kc][1];
            float f02 = sacc[2*kc][2],   f03 = sacc[2*kc][3];
            float f10 = sacc[2*kc+1][0], f11 = sacc[2*kc+1][1];
            float f12 = sacc[2*kc+1][2], f13 = sacc[2*kc+1][3];
            __nv_bfloat16 h00 = __float2bfloat16(f00), h01 = __float2bfloat16(f01);
            __nv_bfloat16 h02 = __float2bfloat16(f02), h03 = __float2bfloat16(f03);
            __nv_bfloat16 h10 = __float2bfloat16(f10), h11 = __float2bfloat16(f11);
            __nv_bfloat16 h12 = __float2bfloat16(f12), h13 = __float2bfloat16(f13);
            uint32_t aH[4], aL[4];
            { __nv_bfloat162 t; t.x=h00; t.y=h01; aH[0]=*(uint32_t*)&t; }
            { __nv_bfloat162 t; t.x=h02; t.y=h03; aH[1]=*(uint32_t*)&t; }
            { __nv_bfloat162 t; t.x=h10; t.y=h11; aH[2]=*(uint32_t*)&t; }
            { __nv_bfloat162 t; t.x=h12; t.y=h13; aH[3]=*(uint32_t*)&t; }
            aL[0] = pack_bf2(f00 - __bfloat162float(h00), f01 - __bfloat162float(h01));
            aL[1] = pack_bf2(f02 - __bfloat162float(h02), f03 - __bfloat162float(h03));
            aL[2] = pack_bf2(f10 - __bfloat162float(h10), f11 - __bfloat162float(h11));
            aL[3] = pack_bf2(f12 - __bfloat162float(h12), f13 - __bfloat162float(h13));

            const uint32_t kb = (uint32_t)(kc * 32);
            uint32_t vH[16], vL[16];
#pragma unroll
            for (int lb = 0; lb < 4; lb++) {
                ldsm4(vH[lb * 4 + 0], vH[lb * 4 + 1], vH[lb * 4 + 2], vH[lb * 4 + 3],
                      vBaseHi + kb + (uint32_t)(lb * 16 * ARS * 2));
                ldsm4(vL[lb * 4 + 0], vL[lb * 4 + 1], vL[lb * 4 + 2], vL[lb * 4 + 3],
                      vBaseLo + kb + (uint32_t)(lb * 16 * ARS * 2));
            }
#pragma unroll
            for (int nt = 0; nt < 8; nt++) {
                const int lo = ((nt >> 1) << 2) + (nt & 1);
                mma16816(oacc[nt], aH, vH[lo], vH[lo + 2]);
                mma16816(oacc[nt], aH, vL[lo], vL[lo + 2]);
                mma16816(oacc[nt], aL, vH[lo], vH[lo + 2]);
            }
        }
    }

    // ---- epilogue ----
    const float inv0 = 1.0f / l0;
    const float inv1 = 1.0f / l1;
    const int row0 = qb * 128 + wid * 16 + (lane >> 2);
#pragma unroll
    for (int nt = 0; nt < 8; nt++) {
        int col = h * DK + nt * 8 + (lane & 3) * 2;
        float* d0 = out + ((size_t)(b * SS + row0)) * DD + col;
        float* d1 = d0 + (size_t)8 * DD;
        *(float2*)d0 = make_float2(oacc[nt][0] * inv0, oacc[nt][1] * inv0);
        *(float2*)d1 = make_float2(oacc[nt][2] * inv1, oacc[nt][3] * inv1);
    }
}

// ---------------------------------------------------------------------------
extern "C" void kernel_launch(void* const* d_in, const int* in_sizes, int n_in,
                              void* d_out, int out_size) {
    const float* x    = (const float*)d_in[0];
    const int*   pos  = (const int*)d_in[1];
    const float* Wqkv = (const float*)d_in[2];
    const float* Wo   = (const float*)d_in[3];
    float* out = (float*)d_out;

    float *qkv = nullptr, *att = nullptr;
    __nv_bfloat16 *ahi = nullptr, *alo = nullptr, *bhi = nullptr, *blo = nullptr;
    cudaGetSymbolAddress((void**)&qkv, g_qkv);
    cudaGetSymbolAddress((void**)&att, g_att);
    cudaGetSymbolAddress((void**)&ahi, g_ahi);
    cudaGetSymbolAddress((void**)&alo, g_alo);
    cudaGetSymbolAddress((void**)&bhi, g_bhi);
    cudaGetSymbolAddress((void**)&blo, g_blo);

    cudaFuncSetAttribute(gemm_mma, cudaFuncAttributeMaxDynamicSharedMemorySize, GEMM_SMEM);
    cudaFuncSetAttribute(attn_mma, cudaFuncAttributeMaxDynamicSharedMemorySize, ATTN_SMEM);

    // 1) split x and Wqkv to bf16 hi/lo
    {
        int n2 = MM * DD / 2;
        split_bf16<<<(n2 + 255) / 256, 256>>>((const float2*)x,
            (__nv_bfloat162*)ahi, (__nv_bfloat162*)alo, n2);
        int w2 = D3 * DD / 2;
        split_bf16<<<(w2 + 255) / 256, 256>>>((const float2*)Wqkv,
            (__nv_bfloat162*)bhi, (__nv_bfloat162*)blo, w2);
    }

    // 2) QKV projection: [8192,1024] x [3072,1024]^T
    {
        dim3 grid(D3 / 128, MM / 128);
        gemm_mma<<<grid, 256, GEMM_SMEM>>>(ahi, alo, bhi, blo, qkv, D3, DD);
    }

    // 3) RoPE on q,k in place
    {
        int total = BB * SS * HH * (DK / 2);
        rope_kernel<<<(total + 255) / 256, 256>>>(qkv, pos);
    }

    // 4) Causal flash attention (tensor cores)
    {
        dim3 grid(SS / 128, HH, BB);
        attn_mma<<<grid, 256, ATTN_SMEM>>>(qkv, att);
    }

    // 5) split att and Wo, then output projection
    {
        int n2 = MM * DD / 2;
        split_bf16<<<(n2 + 255) / 256, 256>>>((const float2*)att,
            (__nv_bfloat162*)ahi, (__nv_bfloat162*)alo, n2);
        int w2 = DD * DD / 2;
        split_bf16<<<(w2 + 255) / 256, 256>>>((const float2*)Wo,
            (__nv_bfloat162*)bhi, (__nv_bfloat162*)blo, w2);
        dim3 grid(DD / 128, MM / 128);
        gemm_mma<<<grid, 256, GEMM_SMEM>>>(ahi, alo, bhi, blo, out, DD, DD);
    }
}

// round 9
// speedup vs baseline: 2.2917x; 1.1458x over previous
#include <cuda_runtime.h>
#include <cuda_bf16.h>
#include <cstdint>
#include <cstdio>

// Problem constants
#define BB 4
#define SS 2048
#define DD 1024
#define HH 16
#define DK 64
#define D3 3072
#define MM (BB*SS)          // 8192

// Scratch (device globals: allocation-free contract)
__device__ float g_qkv[(size_t)MM * D3];   // [B*S, 3D] : q | k | v
__device__ __nv_bfloat16 g_ahi[(size_t)MM * DD];
__device__ __nv_bfloat16 g_alo[(size_t)MM * DD];
__device__ __nv_bfloat16 g_bhi[(size_t)D3 * DD];
__device__ __nv_bfloat16 g_blo[(size_t)D3 * DD];
__device__ __nv_bfloat16 g_khi[(size_t)MM * DD];   // [b,h,s,dk]
__device__ __nv_bfloat16 g_klo[(size_t)MM * DD];
__device__ __nv_bfloat16 g_vthi[(size_t)MM * DD];  // [b,h,dk,s]
__device__ __nv_bfloat16 g_vtlo[(size_t)MM * DD];

// ---------------------------------------------------------------------------
// helpers
// ---------------------------------------------------------------------------
__device__ __forceinline__ uint32_t smem_u32(const void* p) {
    uint32_t a;
    asm("{ .reg .u64 t; cvta.to.shared.u64 t, %1; cvt.u32.u64 %0, t; }" : "=r"(a) : "l"(p));
    return a;
}
__device__ __forceinline__ void ldsm4(uint32_t& r0, uint32_t& r1, uint32_t& r2,
                                      uint32_t& r3, uint32_t addr) {
    asm volatile("ldmatrix.sync.aligned.m8n8.x4.shared.b16 {%0,%1,%2,%3}, [%4];"
                 : "=r"(r0), "=r"(r1), "=r"(r2), "=r"(r3) : "r"(addr));
}
__device__ __forceinline__ void mma16816(float* c, const uint32_t* a,
                                         uint32_t b0, uint32_t b1) {
    asm volatile(
        "mma.sync.aligned.m16n8k16.row.col.f32.bf16.bf16.f32 "
        "{%0,%1,%2,%3}, {%4,%5,%6,%7}, {%8,%9}, {%0,%1,%2,%3};"
        : "+f"(c[0]), "+f"(c[1]), "+f"(c[2]), "+f"(c[3])
        : "r"(a[0]), "r"(a[1]), "r"(a[2]), "r"(a[3]), "r"(b0), "r"(b1));
}
__device__ __forceinline__ uint32_t pack_bf2(float a, float b) {
    __nv_bfloat162 t = __floats2bfloat162_rn(a, b);
    return *(uint32_t*)&t;
}
__device__ __forceinline__ void cp16(uint32_t dst, const void* src) {
    asm volatile("cp.async.cg.shared.global [%0], [%1], 16;" :: "r"(dst), "l"(src));
}
#define CP_COMMIT() asm volatile("cp.async.commit_group;" ::: "memory")
#define CP_WAIT(n)  asm volatile("cp.async.wait_group %0;" :: "n"(n) : "memory")

// ---------------------------------------------------------------------------
// Split fp32 -> bf16 hi + bf16 lo (2 elements per thread)
// ---------------------------------------------------------------------------
__global__ __launch_bounds__(256) void split_bf16(const float2* __restrict__ x,
                                                  __nv_bfloat162* __restrict__ hi,
                                                  __nv_bfloat162* __restrict__ lo,
                                                  int n2) {
    int i = blockIdx.x * blockDim.x + threadIdx.x;
    if (i >= n2) return;
    float2 v = x[i];
    __nv_bfloat16 hx = __float2bfloat16(v.x);
    __nv_bfloat16 hy = __float2bfloat16(v.y);
    float rx = v.x - __bfloat162float(hx);
    float ry = v.y - __bfloat162float(hy);
    __nv_bfloat162 h; h.x = hx; h.y = hy;
    hi[i] = h;
    lo[i] = __floats2bfloat162_rn(rx, ry);
}

// ---------------------------------------------------------------------------
// Warp-MMA bf16 split-2 GEMM (NT): unchanged proven version.
// ---------------------------------------------------------------------------
#define RS 72
#define TILE_SMB (128 * RS * 2)
#define GEMM_SMEM (4 * TILE_SMB)

__global__ __launch_bounds__(256) void gemm_mma(
    const __nv_bfloat16* __restrict__ Ahi, const __nv_bfloat16* __restrict__ Alo,
    const __nv_bfloat16* __restrict__ Bhi, const __nv_bfloat16* __restrict__ Blo,
    float* __restrict__ C, int N, int K)
{
    extern __shared__ __align__(16) __nv_bfloat16 sm[];
    __nv_bfloat16* tile[4] = { sm, sm + 128 * RS, sm + 2 * 128 * RS, sm + 3 * 128 * RS };

    const int tid  = threadIdx.x;
    const int lane = tid & 31;
    const int wid  = tid >> 5;
    const int wm   = wid & 1;
    const int wn   = wid >> 1;
    const int m0 = blockIdx.y * 128;
    const int n0 = blockIdx.x * 128;

    const __nv_bfloat16* srcs[4] = { Ahi + (size_t)m0 * K, Alo + (size_t)m0 * K,
                                     Bhi + (size_t)n0 * K, Blo + (size_t)n0 * K };

    const int lrow  = (lane & 7) + ((lane >> 3) & 1) * 8;
    const int lkadd = (lane >> 4) * 8;

    const uint32_t smb = smem_u32(sm);
    const uint32_t aBaseHi = smb + (uint32_t)((wm * 64 + lrow) * RS + lkadd) * 2;
    const uint32_t aBaseLo = aBaseHi + TILE_SMB;
    const uint32_t bBaseHi = smb + 2 * TILE_SMB +
                             (uint32_t)((wn * 32 + lrow) * RS + lkadd) * 2;
    const uint32_t bBaseLo = bBaseHi + TILE_SMB;

    float acc[4][4][4];
#pragma unroll
    for (int i = 0; i < 4; i++)
#pragma unroll
        for (int j = 0; j < 4; j++)
#pragma unroll
            for (int r = 0; r < 4; r++) acc[i][j][r] = 0.0f;

    const int nStages = K >> 6;
    for (int s = 0; s < nStages; s++) {
        const int k0 = s << 6;
        __syncthreads();
#pragma unroll
        for (int t = 0; t < 4; t++) {
            const __nv_bfloat16* src = srcs[t] + k0;
#pragma unroll
            for (int it = 0; it < 4; it++) {
                int q = it * 256 + tid;
                int r = q >> 3;
                int c = q & 7;
                *(uint4*)(tile[t] + r * RS + c * 8) =
                    *(const uint4*)(src + (size_t)r * K + c * 8);
            }
        }
        __syncthreads();

#pragma unroll
        for (int ks = 0; ks < 4; ks++) {
            const uint32_t kb = (uint32_t)(ks * 16 * 2);
            uint32_t bH[8], bL[8];
            ldsm4(bH[0], bH[1], bH[2], bH[3], bBaseHi + kb);
            ldsm4(bH[4], bH[5], bH[6], bH[7], bBaseHi + kb + 16 * RS * 2);
            ldsm4(bL[0], bL[1], bL[2], bL[3], bBaseLo + kb);
            ldsm4(bL[4], bL[5], bL[6], bL[7], bBaseLo + kb + 16 * RS * 2);
#pragma unroll
            for (int mt = 0; mt < 4; mt++) {
                uint32_t aH[4], aL[4];
                const uint32_t moff = (uint32_t)(mt * 16 * RS * 2);
                ldsm4(aH[0], aH[1], aH[2], aH[3], aBaseHi + moff + kb);
                ldsm4(aL[0], aL[1], aL[2], aL[3], aBaseLo + moff + kb);
#pragma unroll
                for (int nt = 0; nt < 4; nt++) {
                    const int lo = ((nt >> 1) << 2) + (nt & 1);
                    mma16816(acc[mt][nt], aH, bH[lo], bH[lo + 2]);
                    mma16816(acc[mt][nt], aH, bL[lo], bL[lo + 2]);
                    mma16816(acc[mt][nt], aL, bH[lo], bH[lo + 2]);
                }
            }
        }
    }

    const int qrow = lane >> 2;
    const int qcol = (lane & 3) * 2;
#pragma unroll
    for (int mt = 0; mt < 4; mt++) {
#pragma unroll
        for (int nt = 0; nt < 4; nt++) {
            float* base = C + (size_t)(m0 + wm * 64 + mt * 16 + qrow) * N
                            + n0 + wn * 32 + nt * 8 + qcol;
            *(float2*)base = make_float2(acc[mt][nt][0], acc[mt][nt][1]);
            *(float2*)(base + (size_t)8 * N) = make_float2(acc[mt][nt][2], acc[mt][nt][3]);
        }
    }
}

// ---------------------------------------------------------------------------
// RoPE: q in-place (fp32); k -> rope'd, split to bf16 hi/lo in [b,h,s,dk].
// One thread per (b, s, h, pair j).
// ---------------------------------------------------------------------------
__global__ __launch_bounds__(256) void rope_split(float* __restrict__ qkv,
                                                  const int* __restrict__ pos,
                                                  __nv_bfloat16* __restrict__ khi,
                                                  __nv_bfloat16* __restrict__ klo) {
    int p = blockIdx.x * blockDim.x + threadIdx.x;
    if (p >= BB * SS * HH * (DK / 2)) return;
    int j = p & 31;
    int h = (p >> 5) & (HH - 1);
    int s = (p >> 9) & (SS - 1);
    int b = p >> 20;

    float e   = -(float)(2 * j) / (float)DK;
    float inv = powf(10000.0f, e);
    float ang = (float)pos[s] * inv;
    float sn, cs;
    sincosf(ang, &sn, &cs);

    size_t base = ((size_t)(b * SS + s)) * D3 + h * DK + 2 * j;
    float q1 = qkv[base], q2 = qkv[base + 1];
    qkv[base]     = q1 * cs - q2 * sn;
    qkv[base + 1] = q1 * sn + q2 * cs;

    float k1 = qkv[base + DD], k2 = qkv[base + DD + 1];
    float r1 = k1 * cs - k2 * sn;
    float r2 = k1 * sn + k2 * cs;
    __nv_bfloat16 h1 = __float2bfloat16(r1);
    __nv_bfloat16 h2 = __float2bfloat16(r2);
    size_t kdst = (((size_t)(b * HH + h) * SS + s)) * DK + 2 * j;
    __nv_bfloat162 hp; hp.x = h1; hp.y = h2;
    *(__nv_bfloat162*)(khi + kdst) = hp;
    *(__nv_bfloat162*)(klo + kdst) =
        __floats2bfloat162_rn(r1 - __bfloat162float(h1), r2 - __bfloat162float(h2));
}

// ---------------------------------------------------------------------------
// V: transpose + split -> vthi/vtlo [b,h,dk,S]. Tile 64s x 64d via smem.
// grid (SS/64, BB*HH), 256 threads.
// ---------------------------------------------------------------------------
__global__ __launch_bounds__(256) void splitv_t(const float* __restrict__ qkv,
                                                __nv_bfloat16* __restrict__ vthi,
                                                __nv_bfloat16* __restrict__ vtlo) {
    __shared__ float t[64][65];
    const int tid = threadIdx.x;
    const int s0 = blockIdx.x * 64;
    const int bh = blockIdx.y;
    const int b = bh >> 4, h = bh & 15;

#pragma unroll
    for (int it = 0; it < 4; it++) {
        int idx = it * 256 + tid;
        int sl = idx >> 4;
        int d4 = (idx & 15) * 4;
        float4 v = *(const float4*)(qkv + ((size_t)(b * SS + s0 + sl)) * D3
                                    + 2 * DD + h * DK + d4);
        t[sl][d4 + 0] = v.x; t[sl][d4 + 1] = v.y;
        t[sl][d4 + 2] = v.z; t[sl][d4 + 3] = v.w;
    }
    __syncthreads();

    const int d  = tid >> 2;
    const int sc = (tid & 3) * 16;
    __nv_bfloat16 hv[16], lv[16];
#pragma unroll
    for (int j = 0; j < 16; j++) {
        float v = t[sc + j][d];
        hv[j] = __float2bfloat16(v);
        lv[j] = __float2bfloat16(v - __bfloat162float(hv[j]));
    }
    size_t dst = ((size_t)(b * HH + h) * DK + d) * SS + s0 + sc;
    *(uint4*)(vthi + dst)     = *(uint4*)&hv[0];
    *(uint4*)(vthi + dst + 8) = *(uint4*)&hv[8];
    *(uint4*)(vtlo + dst)     = *(uint4*)&lv[0];
    *(uint4*)(vtlo + dst + 8) = *(uint4*)&lv[8];
}

// ---------------------------------------------------------------------------
// Tensor-core causal flash attention, cp.async double-buffered tiles.
// Stage = {Khi, Klo, Vthi, Vtlo} each [64][72] bf16 = 36864 B; 2 stages.
// Q staged through buffer 1 (fp32 load + split), fragments held in regs.
// Output written directly as bf16 hi/lo (A operand of out-proj).
// ---------------------------------------------------------------------------
#define ARS 72
#define STAGE_ELE (4 * 64 * ARS)            // 18432 bf16
#define ATTN_SMEM (2 * STAGE_ELE * 2)       // 73728 B

__device__ __forceinline__ void issue_stage(
    uint32_t sbase, const __nv_bfloat16* pKhi, const __nv_bfloat16* pKlo,
    const __nv_bfloat16* pVh, const __nv_bfloat16* pVl, int tid)
{
#pragma unroll
    for (int i = 0; i < 8; i++) {
        int chunk = i * 256 + tid;      // 2048 x 16B
        int t   = chunk >> 9;
        int c   = chunk & 511;
        int row = c >> 3, col = c & 7;
        uint32_t dst = sbase + (uint32_t)(t * 64 * ARS + row * ARS + col * 8) * 2;
        const __nv_bfloat16* src;
        if (t == 0)      src = pKhi + c * 8;            // contiguous tile
        else if (t == 1) src = pKlo + c * 8;
        else if (t == 2) src = pVh + (size_t)row * SS + col * 8;
        else             src = pVl + (size_t)row * SS + col * 8;
        cp16(dst, src);
    }
}

__global__ __launch_bounds__(256) void attn_mma(
    const float* __restrict__ qkv,
    const __nv_bfloat16* __restrict__ khi, const __nv_bfloat16* __restrict__ klo,
    const __nv_bfloat16* __restrict__ vthi, const __nv_bfloat16* __restrict__ vtlo,
    __nv_bfloat16* __restrict__ ohi, __nv_bfloat16* __restrict__ olo)
{
    extern __shared__ __align__(16) __nv_bfloat16 as_[];
    __nv_bfloat16* buf0 = as_;
    __nv_bfloat16* buf1 = as_ + STAGE_ELE;

    const int tid  = threadIdx.x;
    const int lane = tid & 31;
    const int wid  = tid >> 5;
    const int qb = blockIdx.x;
    const int h  = blockIdx.y;
    const int b  = blockIdx.z;

    // ---- load Q (scaled 1/8) into buf1 as hi/lo ----
    __nv_bfloat16* Qhi = buf1;
    __nv_bfloat16* Qlo = buf1 + 128 * ARS;
#pragma unroll
    for (int it = 0; it < 8; it++) {
        int idx = it * 256 + tid;
        int r = idx >> 4;
        int c = (idx & 15) * 4;
        const float* src = qkv + ((size_t)(b * SS + qb * 128 + r)) * D3 + h * DK + c;
        float4 v = *(const float4*)src;
        float f[4] = { v.x * 0.125f, v.y * 0.125f, v.z * 0.125f, v.w * 0.125f };
        __nv_bfloat16 hh[4]; float ll[4];
#pragma unroll
        for (int i = 0; i < 4; i++) { hh[i] = __float2bfloat16(f[i]);
                                      ll[i] = f[i] - __bfloat162float(hh[i]); }
        __nv_bfloat162 p0; p0.x = hh[0]; p0.y = hh[1];
        __nv_bfloat162 p1; p1.x = hh[2]; p1.y = hh[3];
        *(__nv_bfloat162*)(Qhi + r * ARS + c)     = p0;
        *(__nv_bfloat162*)(Qhi + r * ARS + c + 2) = p1;
        *(__nv_bfloat162*)(Qlo + r * ARS + c)     = __floats2bfloat162_rn(ll[0], ll[1]);
        *(__nv_bfloat162*)(Qlo + r * ARS + c + 2) = __floats2bfloat162_rn(ll[2], ll[3]);
    }
    __syncthreads();

    // ---- Q fragments in registers ----
    const int lrow  = (lane & 7) + ((lane >> 3) & 1) * 8;
    const int lkadd = (lane >> 4) * 8;
    const uint32_t qBaseHi = smem_u32(Qhi) + (uint32_t)((wid * 16 + lrow) * ARS + lkadd) * 2;
    const uint32_t qBaseLo = smem_u32(Qlo) + (uint32_t)((wid * 16 + lrow) * ARS + lkadd) * 2;
    uint32_t qh[4][4], ql[4][4];
#pragma unroll
    for (int kc = 0; kc < 4; kc++) {
        ldsm4(qh[kc][0], qh[kc][1], qh[kc][2], qh[kc][3], qBaseHi + kc * 32);
        ldsm4(ql[kc][0], ql[kc][1], ql[kc][2], ql[kc][3], qBaseLo + kc * 32);
    }
    __syncthreads();   // all warps done reading Q before buf1 is reused

    // gmem tile base pointers (per b,h)
    const size_t kvbase = (size_t)(b * HH + h) * SS * DK;
    const __nv_bfloat16* pKhi0 = khi  + kvbase;
    const __nv_bfloat16* pKlo0 = klo  + kvbase;
    const __nv_bfloat16* pVh0  = vthi + kvbase;   // [dk][S]
    const __nv_bfloat16* pVl0  = vtlo + kvbase;

    const uint32_t sb[2] = { smem_u32(buf0), smem_u32(buf1) };
    const uint32_t fragOff  = (uint32_t)(lrow * ARS + lkadd) * 2;

    float oacc[8][4];
#pragma unroll
    for (int nt = 0; nt < 8; nt++)
#pragma unroll
        for (int r = 0; r < 4; r++) oacc[nt][r] = 0.0f;
    float m0 = -1e30f, m1 = -1e30f, l0 = 0.0f, l1 = 0.0f;

    const int grow0 = qb * 128 + wid * 16 + (lane >> 2);
    const int grow1 = grow0 + 8;
    const int nkt = 2 * qb + 2;

    // prologue: stage 0 -> buf0
    issue_stage(sb[0], pKhi0, pKlo0, pVh0, pVl0, tid);
    CP_COMMIT();

    for (int kt = 0; kt < nkt; kt++) {
        if (kt + 1 < nkt) {
            int o = (kt + 1) * 64;
            issue_stage(sb[(kt + 1) & 1], pKhi0 + o * DK, pKlo0 + o * DK,
                        pVh0 + o, pVl0 + o, tid);
            CP_COMMIT();
            CP_WAIT(1);
        } else {
            CP_WAIT(0);
        }
        __syncthreads();

        const uint32_t cur = sb[kt & 1];
        const uint32_t kBaseHi = cur + fragOff;
        const uint32_t kBaseLo = cur + (uint32_t)(64 * ARS * 2) + fragOff;
        const uint32_t vBaseHi = cur + (uint32_t)(2 * 64 * ARS * 2) + fragOff;
        const uint32_t vBaseLo = cur + (uint32_t)(3 * 64 * ARS * 2) + fragOff;

        // ---- S = Q K^T (split-2, 3 passes) ----
        float sacc[8][4];
#pragma unroll
        for (int nt = 0; nt < 8; nt++)
#pragma unroll
            for (int r = 0; r < 4; r++) sacc[nt][r] = 0.0f;

#pragma unroll
        for (int kc = 0; kc < 4; kc++) {
            const uint32_t kb = (uint32_t)(kc * 32);
            uint32_t bH[16], bL[16];
#pragma unroll
            for (int lb = 0; lb < 4; lb++) {
                ldsm4(bH[lb * 4 + 0], bH[lb * 4 + 1], bH[lb * 4 + 2], bH[lb * 4 + 3],
                      kBaseHi + kb + (uint32_t)(lb * 16 * ARS * 2));
                ldsm4(bL[lb * 4 + 0], bL[lb * 4 + 1], bL[lb * 4 + 2], bL[lb * 4 + 3],
                      kBaseLo + kb + (uint32_t)(lb * 16 * ARS * 2));
            }
#pragma unroll
            for (int nt = 0; nt < 8; nt++) {
                const int lo = ((nt >> 1) << 2) + (nt & 1);
                mma16816(sacc[nt], qh[kc], bH[lo], bH[lo + 2]);
                mma16816(sacc[nt], qh[kc], bL[lo], bL[lo + 2]);
                mma16816(sacc[nt], ql[kc], bH[lo], bH[lo + 2]);
            }
        }

        // ---- causal mask ----
        if (kt * 64 + 63 > qb * 128 + wid * 16) {
#pragma unroll
            for (int nt = 0; nt < 8; nt++) {
                int col = kt * 64 + nt * 8 + (lane & 3) * 2;
                if (col > grow0)     sacc[nt][0] = -1e30f;
                if (col + 1 > grow0) sacc[nt][1] = -1e30f;
                if (col > grow1)     sacc[nt][2] = -1e30f;
                if (col + 1 > grow1) sacc[nt][3] = -1e30f;
            }
        }

        // ---- online softmax ----
        float mx0 = -1e30f, mx1 = -1e30f;
#pragma unroll
        for (int nt = 0; nt < 8; nt++) {
            mx0 = fmaxf(mx0, fmaxf(sacc[nt][0], sacc[nt][1]));
            mx1 = fmaxf(mx1, fmaxf(sacc[nt][2], sacc[nt][3]));
        }
        mx0 = fmaxf(mx0, __shfl_xor_sync(0xffffffffu, mx0, 1));
        mx0 = fmaxf(mx0, __shfl_xor_sync(0xffffffffu, mx0, 2));
        mx1 = fmaxf(mx1, __shfl_xor_sync(0xffffffffu, mx1, 1));
        mx1 = fmaxf(mx1, __shfl_xor_sync(0xffffffffu, mx1, 2));
        float mn0 = fmaxf(m0, mx0), mn1 = fmaxf(m1, mx1);
        float cr0 = __expf(m0 - mn0), cr1 = __expf(m1 - mn1);
        float ps0 = 0.0f, ps1 = 0.0f;
#pragma unroll
        for (int nt = 0; nt < 8; nt++) {
            sacc[nt][0] = __expf(sacc[nt][0] - mn0);
            sacc[nt][1] = __expf(sacc[nt][1] - mn0);
            sacc[nt][2] = __expf(sacc[nt][2] - mn1);
            sacc[nt][3] = __expf(sacc[nt][3] - mn1);
            ps0 += sacc[nt][0] + sacc[nt][1];
            ps1 += sacc[nt][2] + sacc[nt][3];
        }
        ps0 += __shfl_xor_sync(0xffffffffu, ps0, 1);
        ps0 += __shfl_xor_sync(0xffffffffu, ps0, 2);
        ps1 += __shfl_xor_sync(0xffffffffu, ps1, 1);
        ps1 += __shfl_xor_sync(0xffffffffu, ps1, 2);
        l0 = l0 * cr0 + ps0;
        l1 = l1 * cr1 + ps1;
        m0 = mn0; m1 = mn1;
#pragma unroll
        for (int nt = 0; nt < 8; nt++) {
            oacc[nt][0] *= cr0; oacc[nt][1] *= cr0;
            oacc[nt][2] *= cr1; oacc[nt][3] *= cr1;
        }

        // ---- O += P V (split-2, 3 passes) ----
#pragma unroll
        for (int kc = 0; kc < 4; kc++) {
            float f00 = sacc[2*kc][0],   f01 = sacc[2*kc][1];
            float f02 = sacc[2*kc][2],   f03 = sacc[2*kc][3];
            float f10 = sacc[2*kc+1][0], f11 = sacc[2*kc+1][1];
            float f12 = sacc[2*kc+1][2], f13 = sacc[2*kc+1][3];
            __nv_bfloat16 h00 = __float2bfloat16(f00), h01 = __float2bfloat16(f01);
            __nv_bfloat16 h02 = __float2bfloat16(f02), h03 = __float2bfloat16(f03);
            __nv_bfloat16 h10 = __float2bfloat16(f10), h11 = __float2bfloat16(f11);
            __nv_bfloat16 h12 = __float2bfloat16(f12), h13 = __float2bfloat16(f13);
            uint32_t aH[4], aL[4];
            { __nv_bfloat162 t; t.x=h00; t.y=h01; aH[0]=*(uint32_t*)&t; }
            { __nv_bfloat162 t; t.x=h02; t.y=h03; aH[1]=*(uint32_t*)&t; }
            { __nv_bfloat162 t; t.x=h10; t.y=h11; aH[2]=*(uint32_t*)&t; }
            { __nv_bfloat162 t; t.x=h12; t.y=h13; aH[3]=*(uint32_t*)&t; }
            aL[0] = pack_bf2(f00 - __bfloat162float(h00), f01 - __bfloat162float(h01));
            aL[1] = pack_bf2(f02 - __bfloat162float(h02), f03 - __bfloat162float(h03));
            aL[2] = pack_bf2(f10 - __bfloat162float(h10), f11 - __bfloat162float(h11));
            aL[3] = pack_bf2(f12 - __bfloat162float(h12), f13 - __bfloat162float(h13));

            const uint32_t kb = (uint32_t)(kc * 32);
            uint32_t vH[16], vL[16];
#pragma unroll
            for (int lb = 0; lb < 4; lb++) {
                ldsm4(vH[lb * 4 + 0], vH[lb * 4 + 1], vH[lb * 4 + 2], vH[lb * 4 + 3],
                      vBaseHi + kb + (uint32_t)(lb * 16 * ARS * 2));
                ldsm4(vL[lb * 4 + 0], vL[lb * 4 + 1], vL[lb * 4 + 2], vL[lb * 4 + 3],
                      vBaseLo + kb + (uint32_t)(lb * 16 * ARS * 2));
            }
#pragma unroll
            for (int nt = 0; nt < 8; nt++) {
                const int lo = ((nt >> 1) << 2) + (nt & 1);
                mma16816(oacc[nt], aH, vH[lo], vH[lo + 2]);
                mma16816(oacc[nt], aH, vL[lo], vL[lo + 2]);
                mma16816(oacc[nt], aL, vH[lo], vH[lo + 2]);
            }
        }
        __syncthreads();   // all reads of cur done before it is overwritten
    }

    // ---- epilogue: write output as bf16 hi/lo ----
    const float inv0 = 1.0f / l0;
    const float inv1 = 1.0f / l1;
    const int row0 = qb * 128 + wid * 16 + (lane >> 2);
#pragma unroll
    for (int nt = 0; nt < 8; nt++) {
        int col = h * DK + nt * 8 + (lane & 3) * 2;
        size_t d0 = ((size_t)(b * SS + row0)) * DD + col;
        size_t d1 = d0 + (size_t)8 * DD;
        float v00 = oacc[nt][0] * inv0, v01 = oacc[nt][1] * inv0;
        float v10 = oacc[nt][2] * inv1, v11 = oacc[nt][3] * inv1;
        __nv_bfloat16 a = __float2bfloat16(v00), c = __float2bfloat16(v01);
        __nv_bfloat16 d = __float2bfloat16(v10), e = __float2bfloat16(v11);
        { __nv_bfloat162 t; t.x = a; t.y = c; *(__nv_bfloat162*)(ohi + d0) = t; }
        { __nv_bfloat162 t; t.x = d; t.y = e; *(__nv_bfloat162*)(ohi + d1) = t; }
        *(__nv_bfloat162*)(olo + d0) =
            __floats2bfloat162_rn(v00 - __bfloat162float(a), v01 - __bfloat162float(c));
        *(__nv_bfloat162*)(olo + d1) =
            __floats2bfloat162_rn(v10 - __bfloat162float(d), v11 - __bfloat162float(e));
    }
}

// ---------------------------------------------------------------------------
extern "C" void kernel_launch(void* const* d_in, const int* in_sizes, int n_in,
                              void* d_out, int out_size) {
    const float* x    = (const float*)d_in[0];
    const int*   pos  = (const int*)d_in[1];
    const float* Wqkv = (const float*)d_in[2];
    const float* Wo   = (const float*)d_in[3];
    float* out = (float*)d_out;

    float *qkv = nullptr;
    __nv_bfloat16 *ahi, *alo, *bhi, *blo, *khi, *klo, *vthi, *vtlo;
    cudaGetSymbolAddress((void**)&qkv, g_qkv);
    cudaGetSymbolAddress((void**)&ahi, g_ahi);
    cudaGetSymbolAddress((void**)&alo, g_alo);
    cudaGetSymbolAddress((void**)&bhi, g_bhi);
    cudaGetSymbolAddress((void**)&blo, g_blo);
    cudaGetSymbolAddress((void**)&khi, g_khi);
    cudaGetSymbolAddress((void**)&klo, g_klo);
    cudaGetSymbolAddress((void**)&vthi, g_vthi);
    cudaGetSymbolAddress((void**)&vtlo, g_vtlo);

    cudaFuncSetAttribute(gemm_mma, cudaFuncAttributeMaxDynamicSharedMemorySize, GEMM_SMEM);
    cudaFuncSetAttribute(attn_mma, cudaFuncAttributeMaxDynamicSharedMemorySize, ATTN_SMEM);

    // 1) split x and Wqkv to bf16 hi/lo
    {
        int n2 = MM * DD / 2;
        split_bf16<<<(n2 + 255) / 256, 256>>>((const float2*)x,
            (__nv_bfloat162*)ahi, (__nv_bfloat162*)alo, n2);
        int w2 = D3 * DD / 2;
        split_bf16<<<(w2 + 255) / 256, 256>>>((const float2*)Wqkv,
            (__nv_bfloat162*)bhi, (__nv_bfloat162*)blo, w2);
    }

    // 2) QKV projection: [8192,1024] x [3072,1024]^T
    {
        dim3 grid(D3 / 128, MM / 128);
        gemm_mma<<<grid, 256, GEMM_SMEM>>>(ahi, alo, bhi, blo, qkv, D3, DD);
    }

    // 3) RoPE (q in place, k split to bf16) + V transpose-split
    {
        int total = BB * SS * HH * (DK / 2);
        rope_split<<<(total + 255) / 256, 256>>>(qkv, pos, khi, klo);
        dim3 gv(SS / 64, BB * HH);
        splitv_t<<<gv, 256>>>(qkv, vthi, vtlo);
    }

    // 4) Causal flash attention (tensor cores, cp.async pipelined);
    //    writes output directly as bf16 hi/lo into ahi/alo
    {
        dim3 grid(SS / 128, HH, BB);
        attn_mma<<<grid, 256, ATTN_SMEM>>>(qkv, khi, klo, vthi, vtlo, ahi, alo);
    }

    // 5) split Wo, then output projection to fp32 out
    {
        int w2 = DD * DD / 2;
        split_bf16<<<(w2 + 255) / 256, 256>>>((const float2*)Wo,
            (__nv_bfloat162*)bhi, (__nv_bfloat162*)blo, w2);
        dim3 grid(DD / 128, MM / 128);
        gemm_mma<<<grid, 256, GEMM_SMEM>>>(ahi, alo, bhi, blo, out, DD, DD);
    }
}